// round 1
// baseline (speedup 1.0000x reference)
#include <cuda_runtime.h>
#include <math.h>

#define NN   50000
#define EE   800000
#define DIN_ 32
#define DL_  128
#define DOUT_ 10
#define GG   256
#define KK   3

// ---------------- scratch (device globals: allowed, no runtime alloc) ----------------
__device__ __align__(16) float g_h  [NN * DL_];
__device__ __align__(16) float g_u  [NN * DL_];
__device__ __align__(16) float g_acc[NN * DL_];
__device__ __align__(16) float g_g  [NN * DL_];
__device__ __align__(16) float g_t  [NN * DL_];
__device__ __align__(16) float g_dec1[NN * 256];
__device__ __align__(16) float g_dinv[NN];
__device__ __align__(16) int   g_deg [NN];
__device__ __align__(16) float g_sums[GG * DOUT_];
__device__ __align__(16) float g_cnt [GG];

// ---------------- small utility kernels ----------------
__global__ void count_deg_kernel(const int* __restrict__ dst, int* __restrict__ deg, int E) {
    int i = blockIdx.x * blockDim.x + threadIdx.x;
    if (i < E) atomicAdd(&deg[dst[i]], 1);
}

__global__ void calc_dinv_kernel(const int* __restrict__ deg, float* __restrict__ dinv, int M) {
    int i = blockIdx.x * blockDim.x + threadIdx.x;
    if (i < M) dinv[i] = rsqrtf((float)deg[i] + 1.0f);
}

__global__ void count_nodes_kernel(const int* __restrict__ batch, float* __restrict__ cnt, int M) {
    int i = blockIdx.x * blockDim.x + threadIdx.x;
    if (i < M) atomicAdd(&cnt[batch[i]], 1.0f);
}

// g = dinv[row] * (acc + u) + b_gcn[col]      (one float4 per thread)
__global__ void combine_kernel(const float* __restrict__ acc, const float* __restrict__ u,
                               const float* __restrict__ dinv, const float* __restrict__ bgcn,
                               float* __restrict__ g, int M) {
    int i = blockIdx.x * blockDim.x + threadIdx.x;           // float4 index over M*32
    if (i >= M * (DL_ / 4)) return;
    int row = i >> 5;
    int c4  = (i & 31) * 4;
    float dv = dinv[row];
    float4 a  = *(const float4*)(acc + (size_t)i * 4);
    float4 uu = *(const float4*)(u   + (size_t)i * 4);
    float4 b  = *(const float4*)(bgcn + c4);
    float4 o;
    o.x = dv * (a.x + uu.x) + b.x;
    o.y = dv * (a.y + uu.y) + b.y;
    o.z = dv * (a.z + uu.z) + b.z;
    o.w = dv * (a.w + uu.w) + b.w;
    *(float4*)(g + (size_t)i * 4) = o;
}

// h = mu + std * eps
__global__ void reparam_kernel(const float* __restrict__ mu, const float* __restrict__ st,
                               const float* __restrict__ eps, float* __restrict__ h, int n4) {
    int i = blockIdx.x * blockDim.x + threadIdx.x;
    if (i >= n4) return;
    float4 m = *(const float4*)(mu  + (size_t)i * 4);
    float4 s = *(const float4*)(st  + (size_t)i * 4);
    float4 e = *(const float4*)(eps + (size_t)i * 4);
    float4 o;
    o.x = fmaf(s.x, e.x, m.x);
    o.y = fmaf(s.y, e.y, m.y);
    o.z = fmaf(s.z, e.z, m.z);
    o.w = fmaf(s.w, e.w, m.w);
    *(float4*)(h + (size_t)i * 4) = o;
}

// acc[dst] += u[src]   one warp per edge, red.global.add.v4.f32 (sm_90+)
__global__ void edge_scatter_kernel(const int* __restrict__ src, const int* __restrict__ dst,
                                    const float* __restrict__ u, float* __restrict__ acc, int E) {
    int w    = (blockIdx.x * blockDim.x + threadIdx.x) >> 5;
    int lane = threadIdx.x & 31;
    if (w >= E) return;
    int s = src[w];
    int d = dst[w];
    float4 v = *(const float4*)(u + (size_t)s * DL_ + lane * 4);
    float* a = acc + (size_t)d * DL_ + lane * 4;
    asm volatile("red.global.add.v4.f32 [%0], {%1,%2,%3,%4};"
                 :: "l"(a), "f"(v.x), "f"(v.y), "f"(v.z), "f"(v.w) : "memory");
}

// ---------------- generic SGEMM: C = act(A[M,K] @ B[K,Nc] + bias) * rowscale ----------------
// 128x128 block tile, BK=8, 256 threads, 8x8 microtile.
// act: 0=none, 1=sigmoid, 2=relu, 3=softplus(v + bias - 5)
__global__ __launch_bounds__(256, 2)
void gemm_bias_act(const float* __restrict__ A, const float* __restrict__ B,
                   const float* __restrict__ bias, const float* __restrict__ rowscale,
                   float* __restrict__ C, int M, int K, int Nc, int act) {
    __shared__ float As[8][128];
    __shared__ float Bs[8][128];
    const int brow = blockIdx.x * 128;
    const int bcol = blockIdx.y * 128;
    const int tid  = threadIdx.x;
    const int tx   = tid & 15;
    const int ty   = tid >> 4;
    const int arow = tid >> 1;
    const int acol = (tid & 1) * 4;
    const int bkr  = tid >> 5;
    const int bc4  = (tid & 31) * 4;

    float acc[8][8];
#pragma unroll
    for (int i = 0; i < 8; i++)
#pragma unroll
        for (int j = 0; j < 8; j++) acc[i][j] = 0.0f;

    for (int k0 = 0; k0 < K; k0 += 8) {
        float4 av = make_float4(0.f, 0.f, 0.f, 0.f);
        int gr = brow + arow;
        if (gr < M) av = *(const float4*)(A + (size_t)gr * K + k0 + acol);
        As[acol + 0][arow] = av.x;
        As[acol + 1][arow] = av.y;
        As[acol + 2][arow] = av.z;
        As[acol + 3][arow] = av.w;
        float4 bv = *(const float4*)(B + (size_t)(k0 + bkr) * Nc + bcol + bc4);
        *(float4*)&Bs[bkr][bc4] = bv;
        __syncthreads();
#pragma unroll
        for (int kk = 0; kk < 8; kk++) {
            float ar[8], br[8];
            *(float4*)&ar[0] = *(const float4*)&As[kk][ty * 8];
            *(float4*)&ar[4] = *(const float4*)&As[kk][ty * 8 + 4];
            *(float4*)&br[0] = *(const float4*)&Bs[kk][tx * 8];
            *(float4*)&br[4] = *(const float4*)&Bs[kk][tx * 8 + 4];
#pragma unroll
            for (int i = 0; i < 8; i++)
#pragma unroll
                for (int j = 0; j < 8; j++) acc[i][j] = fmaf(ar[i], br[j], acc[i][j]);
        }
        __syncthreads();
    }

#pragma unroll
    for (int i = 0; i < 8; i++) {
        int row = brow + ty * 8 + i;
        if (row >= M) continue;
        float rs = rowscale ? rowscale[row] : 1.0f;
#pragma unroll
        for (int j = 0; j < 8; j++) {
            int col = bcol + tx * 8 + j;
            float v = acc[i][j];
            if (bias) v += bias[col];
            if (act == 1)      v = 1.0f / (1.0f + expf(-v));
            else if (act == 2) v = fmaxf(v, 0.0f);
            else if (act == 3) { v -= 5.0f; v = (v > 20.0f) ? v : log1pf(expf(v)); }
            v *= rs;
            C[(size_t)row * Nc + col] = v;
        }
    }
}

// ---------------- fused decoder tail: [N,128] -> 64 -> 32 -> 16 -> 10 -> sigmoid -> pool-sum ----------------
__global__ __launch_bounds__(256)
void decoder_tail_kernel(const float* __restrict__ din,
                         const float* __restrict__ W2, const float* __restrict__ b2,
                         const float* __restrict__ W3, const float* __restrict__ b3,
                         const float* __restrict__ W4, const float* __restrict__ b4,
                         const float* __restrict__ Wo, const float* __restrict__ bo,
                         const int* __restrict__ batch, float* __restrict__ sums, int M) {
    __shared__ float w3[64 * 32];
    __shared__ float w4[32 * 16];
    __shared__ float wo[16 * 10];
    __shared__ float xs [8][128];
    __shared__ float t64[8][64];
    __shared__ float t32[8][32];
    __shared__ float t16[8][16];
    for (int i = threadIdx.x; i < 64 * 32; i += 256) w3[i] = W3[i];
    for (int i = threadIdx.x; i < 32 * 16; i += 256) w4[i] = W4[i];
    for (int i = threadIdx.x; i < 160;     i += 256) wo[i] = Wo[i];
    __syncthreads();

    int warp = threadIdx.x >> 5;
    int lane = threadIdx.x & 31;
    int stride = gridDim.x * 8;

    for (int row = blockIdx.x * 8 + warp; row < M; row += stride) {
        *(float4*)&xs[warp][lane * 4] = *(const float4*)(din + (size_t)row * 128 + lane * 4);
        __syncwarp();
        // 128 -> 64 (W2 from global, L1-resident: 32KB broadcast-coalesced)
        float s0 = b2[lane], s1 = b2[lane + 32];
#pragma unroll 4
        for (int k = 0; k < 128; k++) {
            float xv = xs[warp][k];
            s0 = fmaf(xv, __ldg(W2 + k * 64 + lane),      s0);
            s1 = fmaf(xv, __ldg(W2 + k * 64 + lane + 32), s1);
        }
        t64[warp][lane]      = fmaxf(s0, 0.0f);
        t64[warp][lane + 32] = fmaxf(s1, 0.0f);
        __syncwarp();
        // 64 -> 32
        float s = b3[lane];
#pragma unroll 4
        for (int k = 0; k < 64; k++) s = fmaf(t64[warp][k], w3[k * 32 + lane], s);
        t32[warp][lane] = fmaxf(s, 0.0f);
        __syncwarp();
        // 32 -> 16
        if (lane < 16) {
            float t = b4[lane];
#pragma unroll
            for (int k = 0; k < 32; k++) t = fmaf(t32[warp][k], w4[k * 16 + lane], t);
            t16[warp][lane] = fmaxf(t, 0.0f);
        }
        __syncwarp();
        // 16 -> 10, sigmoid, pool-sum
        if (lane < 10) {
            float t = bo[lane];
#pragma unroll
            for (int k = 0; k < 16; k++) t = fmaf(t16[warp][k], wo[k * 10 + lane], t);
            float yp = 1.0f / (1.0f + expf(-t));
            atomicAdd(&sums[batch[row] * 10 + lane], yp);
        }
        __syncwarp();
    }
}

__global__ void pool_finalize_kernel(const float* __restrict__ sums, const float* __restrict__ cnt,
                                     const float* __restrict__ y,
                                     float* __restrict__ out_pred, float* __restrict__ out_y) {
    int i = blockIdx.x * blockDim.x + threadIdx.x;
    if (i < GG * DOUT_) {
        out_pred[i] = sums[i] / fmaxf(cnt[i / DOUT_], 1.0f);
        out_y[i]    = y[i];
    }
}

// ---------------- launch ----------------
extern "C" void kernel_launch(void* const* d_in, const int* in_sizes, int n_in,
                              void* d_out, int out_size) {
    const float* x     = (const float*)d_in[0];
    const int*   ei    = (const int*)  d_in[1];
    const int*   batch = (const int*)  d_in[2];
    const float* y     = (const float*)d_in[3];
    const float* eps   = (const float*)d_in[4];
    const float* W_in  = (const float*)d_in[5];
    const float* b_in  = (const float*)d_in[6];
    const float* W_gcn = (const float*)d_in[7];
    const float* b_gcn = (const float*)d_in[8];
    const float* W_enc = (const float*)d_in[9];
    const float* b_enc = (const float*)d_in[10];
    const float* W_mu  = (const float*)d_in[11];
    const float* b_mu  = (const float*)d_in[12];
    const float* W_std = (const float*)d_in[13];
    const float* b_std = (const float*)d_in[14];
    const float* Wd0 = (const float*)d_in[15]; const float* bd0 = (const float*)d_in[16];
    const float* Wd1 = (const float*)d_in[17]; const float* bd1 = (const float*)d_in[18];
    const float* Wd2 = (const float*)d_in[19]; const float* bd2 = (const float*)d_in[20];
    const float* Wd3 = (const float*)d_in[21]; const float* bd3 = (const float*)d_in[22];
    const float* Wd4 = (const float*)d_in[23]; const float* bd4 = (const float*)d_in[24];
    const float* Wo  = (const float*)d_in[25]; const float* bo  = (const float*)d_in[26];

    float *h, *u, *acc, *gbuf, *tbuf, *dec1, *dinv, *sums, *cnt;
    int* deg;
    cudaGetSymbolAddress((void**)&h,    g_h);
    cudaGetSymbolAddress((void**)&u,    g_u);
    cudaGetSymbolAddress((void**)&acc,  g_acc);
    cudaGetSymbolAddress((void**)&gbuf, g_g);
    cudaGetSymbolAddress((void**)&tbuf, g_t);
    cudaGetSymbolAddress((void**)&dec1, g_dec1);
    cudaGetSymbolAddress((void**)&dinv, g_dinv);
    cudaGetSymbolAddress((void**)&deg,  g_deg);
    cudaGetSymbolAddress((void**)&sums, g_sums);
    cudaGetSymbolAddress((void**)&cnt,  g_cnt);

    float* out      = (float*)d_out;
    float* out_pred = out;
    float* out_mu   = out + GG * DOUT_;
    float* out_std  = out + GG * DOUT_ + (size_t)NN * DL_;
    float* out_y    = out + GG * DOUT_ + (size_t)2 * NN * DL_;

    const int* src = ei;
    const int* dst = ei + EE;

    cudaMemsetAsync(deg,  0, NN * sizeof(int));
    cudaMemsetAsync(sums, 0, GG * DOUT_ * sizeof(float));
    cudaMemsetAsync(cnt,  0, GG * sizeof(float));

    count_deg_kernel  <<<(EE + 255) / 256, 256>>>(dst, deg, EE);
    calc_dinv_kernel  <<<(NN + 255) / 256, 256>>>(deg, dinv, NN);
    count_nodes_kernel<<<(NN + 255) / 256, 256>>>(batch, cnt, NN);

    dim3 g128((NN + 127) / 128, 1);
    // input layer: h = sigmoid(x @ W_in + b_in)
    gemm_bias_act<<<g128, 256>>>(x, W_in, b_in, nullptr, h, NN, DIN_, DL_, 1);

    int n4 = NN * (DL_ / 4);
    for (int it = 0; it < KK; it++) {
        // u = (h @ W_gcn) * dinv[row]
        gemm_bias_act<<<g128, 256>>>(h, W_gcn, nullptr, dinv, u, NN, DL_, DL_, 0);
        cudaMemsetAsync(acc, 0, (size_t)NN * DL_ * sizeof(float));
        edge_scatter_kernel<<<(EE * 32 + 255) / 256, 256>>>(src, dst, u, acc, EE);
        combine_kernel<<<(n4 + 255) / 256, 256>>>(acc, u, dinv, b_gcn, gbuf, NN);

        const float* cur = gbuf;
        float* nxt = tbuf;
        for (int j = 0; j < 5; j++) {
            gemm_bias_act<<<g128, 256>>>(cur, W_enc + (size_t)j * DL_ * DL_, b_enc + j * DL_,
                                         nullptr, nxt, NN, DL_, DL_, 1);
            float* tmp = (float*)cur; cur = nxt; nxt = tmp;
        }
        // mu / std written straight into d_out regions (last hop's values persist = reference)
        gemm_bias_act<<<g128, 256>>>(cur, W_mu,  b_mu,  nullptr, out_mu,  NN, DL_, DL_, 0);
        gemm_bias_act<<<g128, 256>>>(cur, W_std, b_std, nullptr, out_std, NN, DL_, DL_, 3);
        reparam_kernel<<<(n4 + 255) / 256, 256>>>(out_mu, out_std,
                                                  eps + (size_t)it * NN * DL_, h, n4);
    }

    // decoder
    dim3 gd0((NN + 127) / 128, 2);
    gemm_bias_act<<<gd0, 256>>>(h, Wd0, bd0, nullptr, dec1, NN, DL_, 256, 2);
    gemm_bias_act<<<g128, 256>>>(dec1, Wd1, bd1, nullptr, u, NN, 256, DL_, 2);
    decoder_tail_kernel<<<(NN + 7) / 8, 256>>>(u, Wd2, bd2, Wd3, bd3, Wd4, bd4, Wo, bo,
                                               batch, sums, NN);
    pool_finalize_kernel<<<(GG * DOUT_ + 255) / 256, 256>>>(sums, cnt, y, out_pred, out_y);

    (void)in_sizes; (void)n_in; (void)out_size;
}

// round 2
// speedup vs baseline: 1.1787x; 1.1787x over previous
#include <cuda_runtime.h>
#include <math.h>

#define NN   50000
#define EE   800000
#define DIN_ 32
#define DL_  128
#define DOUT_ 10
#define GG   256
#define KK   3

// ---------------- scratch (device globals) ----------------
__device__ __align__(16) float g_h  [NN * DL_];
__device__ __align__(16) float g_u  [NN * DL_];
__device__ __align__(16) float g_acc[NN * DL_];
__device__ __align__(16) float g_g  [NN * DL_];
__device__ __align__(16) float g_t  [NN * DL_];
__device__ __align__(16) float g_dec1[NN * 256];
__device__ __align__(16) float g_dinv[NN];
__device__ __align__(16) int   g_deg [NN];
__device__ __align__(16) float g_sums[GG * DOUT_];
__device__ __align__(16) float g_cnt [GG];

// ---------------- packed f32x2 helpers ----------------
#define PACK2(out, lo, hi) \
    asm("mov.b64 %0, {%1, %2};" : "=l"(out) : "r"(__float_as_uint(lo)), "r"(__float_as_uint(hi)))
#define UNPACK2(lo, hi, in) \
    do { unsigned _ulo, _uhi; \
         asm("mov.b64 {%0, %1}, %2;" : "=r"(_ulo), "=r"(_uhi) : "l"(in)); \
         lo = __uint_as_float(_ulo); hi = __uint_as_float(_uhi); } while (0)
#define FMA2(d, a, b) \
    asm("fma.rn.f32x2 %0, %1, %2, %0;" : "+l"(d) : "l"(a), "l"(b))

// ---------------- small utility kernels ----------------
__global__ void count_deg_kernel(const int* __restrict__ dst, int* __restrict__ deg, int E) {
    int i = blockIdx.x * blockDim.x + threadIdx.x;
    if (i < E) atomicAdd(&deg[dst[i]], 1);
}

__global__ void calc_dinv_kernel(const int* __restrict__ deg, float* __restrict__ dinv, int M) {
    int i = blockIdx.x * blockDim.x + threadIdx.x;
    if (i < M) dinv[i] = rsqrtf((float)deg[i] + 1.0f);
}

__global__ void count_nodes_kernel(const int* __restrict__ batch, float* __restrict__ cnt, int M) {
    int i = blockIdx.x * blockDim.x + threadIdx.x;
    if (i < M) atomicAdd(&cnt[batch[i]], 1.0f);
}

__global__ void combine_kernel(const float* __restrict__ acc, const float* __restrict__ u,
                               const float* __restrict__ dinv, const float* __restrict__ bgcn,
                               float* __restrict__ g, int M) {
    int i = blockIdx.x * blockDim.x + threadIdx.x;
    if (i >= M * (DL_ / 4)) return;
    int row = i >> 5;
    int c4  = (i & 31) * 4;
    float dv = dinv[row];
    float4 a  = *(const float4*)(acc + (size_t)i * 4);
    float4 uu = *(const float4*)(u   + (size_t)i * 4);
    float4 b  = *(const float4*)(bgcn + c4);
    float4 o;
    o.x = dv * (a.x + uu.x) + b.x;
    o.y = dv * (a.y + uu.y) + b.y;
    o.z = dv * (a.z + uu.z) + b.z;
    o.w = dv * (a.w + uu.w) + b.w;
    *(float4*)(g + (size_t)i * 4) = o;
}

__global__ void reparam_kernel(const float* __restrict__ mu, const float* __restrict__ st,
                               const float* __restrict__ eps, float* __restrict__ h, int n4) {
    int i = blockIdx.x * blockDim.x + threadIdx.x;
    if (i >= n4) return;
    float4 m = *(const float4*)(mu  + (size_t)i * 4);
    float4 s = *(const float4*)(st  + (size_t)i * 4);
    float4 e = *(const float4*)(eps + (size_t)i * 4);
    float4 o;
    o.x = fmaf(s.x, e.x, m.x);
    o.y = fmaf(s.y, e.y, m.y);
    o.z = fmaf(s.z, e.z, m.z);
    o.w = fmaf(s.w, e.w, m.w);
    *(float4*)(h + (size_t)i * 4) = o;
}

// acc[dst] += u[src]   one warp per edge, red.global.add.v4.f32
__global__ void edge_scatter_kernel(const int* __restrict__ src, const int* __restrict__ dst,
                                    const float* __restrict__ u, float* __restrict__ acc, int E) {
    int w    = (blockIdx.x * blockDim.x + threadIdx.x) >> 5;
    int lane = threadIdx.x & 31;
    if (w >= E) return;
    int s = src[w];
    int d = dst[w];
    float4 v = *(const float4*)(u + (size_t)s * DL_ + lane * 4);
    float* a = acc + (size_t)d * DL_ + lane * 4;
    asm volatile("red.global.add.v4.f32 [%0], {%1,%2,%3,%4};"
                 :: "l"(a), "f"(v.x), "f"(v.y), "f"(v.z), "f"(v.w) : "memory");
}

// ---------------- packed-f32x2 SGEMM: C = act(A[M,K] @ B[K,Nc] + bias) * rowscale ----------------
// 64x128 block tile, BK=8, 128 threads, 8x8 microtile, double-buffered smem.
// act: 0=none, 1=sigmoid, 2=relu, 3=softplus(v + bias - 5)
__global__ __launch_bounds__(128, 4)
void gemm_f32x2(const float* __restrict__ A, const float* __restrict__ B,
                const float* __restrict__ bias, const float* __restrict__ rowscale,
                float* __restrict__ C, int M, int K, int Nc, int act) {
    __shared__ float As[2][8][64];
    __shared__ float Bs[2][8][128];
    const int tid  = threadIdx.x;
    const int tx   = tid & 15;          // 16 col groups of 8
    const int ty   = tid >> 4;          // 8 row groups of 8
    const int brow = blockIdx.x * 64;
    const int bcol = blockIdx.y * 128;

    const int arow = tid >> 1;          // 0..63
    const int acol = (tid & 1) * 4;     // 0 or 4
    const int bkr  = tid >> 4;          // 0..7
    const int bc   = (tid & 15) * 8;    // 0..120

    unsigned long long acc2[8][4];
#pragma unroll
    for (int i = 0; i < 8; i++)
#pragma unroll
        for (int j = 0; j < 4; j++) acc2[i][j] = 0ULL;

    const int nk = K >> 3;
    const int gr = brow + arow;

    // preload tile 0
    {
        float4 av = make_float4(0.f, 0.f, 0.f, 0.f);
        if (gr < M) av = *(const float4*)(A + (size_t)gr * K + acol);
        As[0][acol + 0][arow] = av.x;
        As[0][acol + 1][arow] = av.y;
        As[0][acol + 2][arow] = av.z;
        As[0][acol + 3][arow] = av.w;
        float4 bv0 = *(const float4*)(B + (size_t)bkr * Nc + bcol + bc);
        float4 bv1 = *(const float4*)(B + (size_t)bkr * Nc + bcol + bc + 4);
        *(float4*)&Bs[0][bkr][bc]     = bv0;
        *(float4*)&Bs[0][bkr][bc + 4] = bv1;
    }
    __syncthreads();

    for (int it = 0; it < nk; ++it) {
        const int buf = it & 1;
        float4 nav = make_float4(0.f, 0.f, 0.f, 0.f);
        float4 nbv0, nbv1;
        const bool more = (it + 1) < nk;
        if (more) {
            int k0 = (it + 1) * 8;
            if (gr < M) nav = *(const float4*)(A + (size_t)gr * K + k0 + acol);
            nbv0 = *(const float4*)(B + (size_t)(k0 + bkr) * Nc + bcol + bc);
            nbv1 = *(const float4*)(B + (size_t)(k0 + bkr) * Nc + bcol + bc + 4);
        }
#pragma unroll
        for (int kk = 0; kk < 8; ++kk) {
            float ar[8], br[8];
            *(float4*)&ar[0] = *(const float4*)&As[buf][kk][ty * 8];
            *(float4*)&ar[4] = *(const float4*)&As[buf][kk][ty * 8 + 4];
            *(float4*)&br[0] = *(const float4*)&Bs[buf][kk][tx * 8];
            *(float4*)&br[4] = *(const float4*)&Bs[buf][kk][tx * 8 + 4];
            unsigned long long b2[4];
            PACK2(b2[0], br[0], br[1]);
            PACK2(b2[1], br[2], br[3]);
            PACK2(b2[2], br[4], br[5]);
            PACK2(b2[3], br[6], br[7]);
#pragma unroll
            for (int i = 0; i < 8; i++) {
                unsigned long long a2;
                PACK2(a2, ar[i], ar[i]);
                FMA2(acc2[i][0], a2, b2[0]);
                FMA2(acc2[i][1], a2, b2[1]);
                FMA2(acc2[i][2], a2, b2[2]);
                FMA2(acc2[i][3], a2, b2[3]);
            }
        }
        if (more) {
            As[buf ^ 1][acol + 0][arow] = nav.x;
            As[buf ^ 1][acol + 1][arow] = nav.y;
            As[buf ^ 1][acol + 2][arow] = nav.z;
            As[buf ^ 1][acol + 3][arow] = nav.w;
            *(float4*)&Bs[buf ^ 1][bkr][bc]     = nbv0;
            *(float4*)&Bs[buf ^ 1][bkr][bc + 4] = nbv1;
        }
        __syncthreads();
    }

#pragma unroll
    for (int i = 0; i < 8; i++) {
        int row = brow + ty * 8 + i;
        if (row >= M) continue;
        float rs = rowscale ? rowscale[row] : 1.0f;
#pragma unroll
        for (int jp = 0; jp < 4; jp++) {
            float v0, v1;
            UNPACK2(v0, v1, acc2[i][jp]);
            int col = bcol + tx * 8 + jp * 2;
            if (bias) { v0 += bias[col]; v1 += bias[col + 1]; }
            if (act == 1) {
                v0 = 1.0f / (1.0f + expf(-v0));
                v1 = 1.0f / (1.0f + expf(-v1));
            } else if (act == 2) {
                v0 = fmaxf(v0, 0.0f);
                v1 = fmaxf(v1, 0.0f);
            } else if (act == 3) {
                v0 -= 5.0f; v0 = (v0 > 20.0f) ? v0 : log1pf(expf(v0));
                v1 -= 5.0f; v1 = (v1 > 20.0f) ? v1 : log1pf(expf(v1));
            }
            float2 o; o.x = v0 * rs; o.y = v1 * rs;
            *(float2*)(C + (size_t)row * Nc + col) = o;
        }
    }
}

// ---------------- fused decoder tail: [N,128] -> 64 -> 32 -> 16 -> 10 -> sigmoid -> pool-sum ----------------
__global__ __launch_bounds__(128)
void decoder_tail_kernel(const float* __restrict__ din,
                         const float* __restrict__ W2, const float* __restrict__ b2,
                         const float* __restrict__ W3, const float* __restrict__ b3,
                         const float* __restrict__ W4, const float* __restrict__ b4,
                         const float* __restrict__ Wo, const float* __restrict__ bo,
                         const int* __restrict__ batch, float* __restrict__ sums, int M) {
    __shared__ float w2[128 * 64];   // 32 KB
    __shared__ float w3[64 * 32];    // 8 KB
    __shared__ float w4[32 * 16];    // 2 KB
    __shared__ float wo[160];
    __shared__ float xs [4][128];
    __shared__ float t64[4][64];
    __shared__ float t32[4][32];
    __shared__ float t16[4][16];
    for (int i = threadIdx.x; i < 128 * 64; i += 128) w2[i] = W2[i];
    for (int i = threadIdx.x; i < 64 * 32;  i += 128) w3[i] = W3[i];
    for (int i = threadIdx.x; i < 32 * 16;  i += 128) w4[i] = W4[i];
    for (int i = threadIdx.x; i < 160;      i += 128) wo[i] = Wo[i];
    __syncthreads();

    int warp = threadIdx.x >> 5;
    int lane = threadIdx.x & 31;
    int stride = gridDim.x * 4;

    for (int row = blockIdx.x * 4 + warp; row < M; row += stride) {
        *(float4*)&xs[warp][lane * 4] = *(const float4*)(din + (size_t)row * 128 + lane * 4);
        __syncwarp();
        // 128 -> 64
        float s0 = b2[lane], s1 = b2[lane + 32];
#pragma unroll 8
        for (int k = 0; k < 128; k++) {
            float xv = xs[warp][k];
            s0 = fmaf(xv, w2[k * 64 + lane],      s0);
            s1 = fmaf(xv, w2[k * 64 + lane + 32], s1);
        }
        t64[warp][lane]      = fmaxf(s0, 0.0f);
        t64[warp][lane + 32] = fmaxf(s1, 0.0f);
        __syncwarp();
        // 64 -> 32
        float s = b3[lane];
#pragma unroll 8
        for (int k = 0; k < 64; k++) s = fmaf(t64[warp][k], w3[k * 32 + lane], s);
        t32[warp][lane] = fmaxf(s, 0.0f);
        __syncwarp();
        // 32 -> 16
        if (lane < 16) {
            float t = b4[lane];
#pragma unroll
            for (int k = 0; k < 32; k++) t = fmaf(t32[warp][k], w4[k * 16 + lane], t);
            t16[warp][lane] = fmaxf(t, 0.0f);
        }
        __syncwarp();
        // 16 -> 10, sigmoid, pool-sum
        if (lane < 10) {
            float t = bo[lane];
#pragma unroll
            for (int k = 0; k < 16; k++) t = fmaf(t16[warp][k], wo[k * 10 + lane], t);
            float yp = 1.0f / (1.0f + expf(-t));
            atomicAdd(&sums[batch[row] * 10 + lane], yp);
        }
        __syncwarp();
    }
}

__global__ void pool_finalize_kernel(const float* __restrict__ sums, const float* __restrict__ cnt,
                                     const float* __restrict__ y,
                                     float* __restrict__ out_pred, float* __restrict__ out_y) {
    int i = blockIdx.x * blockDim.x + threadIdx.x;
    if (i < GG * DOUT_) {
        out_pred[i] = sums[i] / fmaxf(cnt[i / DOUT_], 1.0f);
        out_y[i]    = y[i];
    }
}

// ---------------- launch ----------------
extern "C" void kernel_launch(void* const* d_in, const int* in_sizes, int n_in,
                              void* d_out, int out_size) {
    const float* x     = (const float*)d_in[0];
    const int*   ei    = (const int*)  d_in[1];
    const int*   batch = (const int*)  d_in[2];
    const float* y     = (const float*)d_in[3];
    const float* eps   = (const float*)d_in[4];
    const float* W_in  = (const float*)d_in[5];
    const float* b_in  = (const float*)d_in[6];
    const float* W_gcn = (const float*)d_in[7];
    const float* b_gcn = (const float*)d_in[8];
    const float* W_enc = (const float*)d_in[9];
    const float* b_enc = (const float*)d_in[10];
    const float* W_mu  = (const float*)d_in[11];
    const float* b_mu  = (const float*)d_in[12];
    const float* W_std = (const float*)d_in[13];
    const float* b_std = (const float*)d_in[14];
    const float* Wd0 = (const float*)d_in[15]; const float* bd0 = (const float*)d_in[16];
    const float* Wd1 = (const float*)d_in[17]; const float* bd1 = (const float*)d_in[18];
    const float* Wd2 = (const float*)d_in[19]; const float* bd2 = (const float*)d_in[20];
    const float* Wd3 = (const float*)d_in[21]; const float* bd3 = (const float*)d_in[22];
    const float* Wd4 = (const float*)d_in[23]; const float* bd4 = (const float*)d_in[24];
    const float* Wo  = (const float*)d_in[25]; const float* bo  = (const float*)d_in[26];

    float *h, *u, *acc, *gbuf, *tbuf, *dec1, *dinv, *sums, *cnt;
    int* deg;
    cudaGetSymbolAddress((void**)&h,    g_h);
    cudaGetSymbolAddress((void**)&u,    g_u);
    cudaGetSymbolAddress((void**)&acc,  g_acc);
    cudaGetSymbolAddress((void**)&gbuf, g_g);
    cudaGetSymbolAddress((void**)&tbuf, g_t);
    cudaGetSymbolAddress((void**)&dec1, g_dec1);
    cudaGetSymbolAddress((void**)&dinv, g_dinv);
    cudaGetSymbolAddress((void**)&deg,  g_deg);
    cudaGetSymbolAddress((void**)&sums, g_sums);
    cudaGetSymbolAddress((void**)&cnt,  g_cnt);

    float* out      = (float*)d_out;
    float* out_pred = out;
    float* out_mu   = out + GG * DOUT_;
    float* out_std  = out + GG * DOUT_ + (size_t)NN * DL_;
    float* out_y    = out + GG * DOUT_ + (size_t)2 * NN * DL_;

    const int* src = ei;
    const int* dst = ei + EE;

    cudaMemsetAsync(deg,  0, NN * sizeof(int));
    cudaMemsetAsync(sums, 0, GG * DOUT_ * sizeof(float));
    cudaMemsetAsync(cnt,  0, GG * sizeof(float));

    count_deg_kernel  <<<(EE + 255) / 256, 256>>>(dst, deg, EE);
    calc_dinv_kernel  <<<(NN + 255) / 256, 256>>>(deg, dinv, NN);
    count_nodes_kernel<<<(NN + 255) / 256, 256>>>(batch, cnt, NN);

    dim3 g64((NN + 63) / 64, 1);
    // input layer: h = sigmoid(x @ W_in + b_in)
    gemm_f32x2<<<g64, 128>>>(x, W_in, b_in, nullptr, h, NN, DIN_, DL_, 1);

    int n4 = NN * (DL_ / 4);
    for (int it = 0; it < KK; it++) {
        // u = (h @ W_gcn) * dinv[row]
        gemm_f32x2<<<g64, 128>>>(h, W_gcn, nullptr, dinv, u, NN, DL_, DL_, 0);
        cudaMemsetAsync(acc, 0, (size_t)NN * DL_ * sizeof(float));
        edge_scatter_kernel<<<(EE * 32 + 255) / 256, 256>>>(src, dst, u, acc, EE);
        combine_kernel<<<(n4 + 255) / 256, 256>>>(acc, u, dinv, b_gcn, gbuf, NN);

        const float* cur = gbuf;
        float* nxt = tbuf;
        for (int j = 0; j < 5; j++) {
            gemm_f32x2<<<g64, 128>>>(cur, W_enc + (size_t)j * DL_ * DL_, b_enc + j * DL_,
                                     nullptr, nxt, NN, DL_, DL_, 1);
            float* tmp = (float*)cur; cur = nxt; nxt = tmp;
        }
        gemm_f32x2<<<g64, 128>>>(cur, W_mu,  b_mu,  nullptr, out_mu,  NN, DL_, DL_, 0);
        gemm_f32x2<<<g64, 128>>>(cur, W_std, b_std, nullptr, out_std, NN, DL_, DL_, 3);
        reparam_kernel<<<(n4 + 255) / 256, 256>>>(out_mu, out_std,
                                                  eps + (size_t)it * NN * DL_, h, n4);
    }

    // decoder
    dim3 gd0((NN + 63) / 64, 2);
    gemm_f32x2<<<gd0, 128>>>(h, Wd0, bd0, nullptr, dec1, NN, DL_, 256, 2);
    gemm_f32x2<<<g64, 128>>>(dec1, Wd1, bd1, nullptr, u, NN, 256, DL_, 2);
    decoder_tail_kernel<<<592, 128>>>(u, Wd2, bd2, Wd3, bd3, Wd4, bd4, Wo, bo,
                                      batch, sums, NN);
    pool_finalize_kernel<<<(GG * DOUT_ + 255) / 256, 256>>>(sums, cnt, y, out_pred, out_y);

    (void)in_sizes; (void)n_in; (void)out_size;
}

// round 3
// speedup vs baseline: 1.2491x; 1.0598x over previous
#include <cuda_runtime.h>
#include <math.h>

#define NN   50000
#define EE   800000
#define DIN_ 32
#define DL_  128
#define DOUT_ 10
#define GG   256
#define KK   3

// ---------------- scratch (device globals) ----------------
__device__ __align__(16) float g_h  [NN * DL_];
__device__ __align__(16) float g_u  [NN * DL_];
__device__ __align__(16) float g_g  [NN * DL_];
__device__ __align__(16) float g_t  [NN * DL_];
__device__ __align__(16) float g_dec1[NN * 256];
__device__ __align__(16) float g_dinv[NN];
__device__ __align__(16) int   g_deg [NN];
__device__ __align__(16) int   g_off [NN + 1];
__device__ __align__(16) int   g_cur [NN];
__device__ __align__(16) int   g_csr [EE];
__device__ __align__(16) float g_sums[GG * DOUT_];
__device__ __align__(16) float g_cnt [GG];

// ---------------- packed f32x2 helpers ----------------
#define PACK2(out, lo, hi) \
    asm("mov.b64 %0, {%1, %2};" : "=l"(out) : "r"(__float_as_uint(lo)), "r"(__float_as_uint(hi)))
#define UNPACK2(lo, hi, in) \
    do { unsigned _ulo, _uhi; \
         asm("mov.b64 {%0, %1}, %2;" : "=r"(_ulo), "=r"(_uhi) : "l"(in)); \
         lo = __uint_as_float(_ulo); hi = __uint_as_float(_uhi); } while (0)
#define FMA2(d, a, b) \
    asm("fma.rn.f32x2 %0, %1, %2, %0;" : "+l"(d) : "l"(a), "l"(b))

// ---------------- one-time graph preprocessing ----------------
__global__ void count_deg_kernel(const int* __restrict__ dst, int* __restrict__ deg, int E) {
    int i = blockIdx.x * blockDim.x + threadIdx.x;
    if (i < E) atomicAdd(&deg[dst[i]], 1);
}

__global__ void calc_dinv_kernel(const int* __restrict__ deg, float* __restrict__ dinv, int M) {
    int i = blockIdx.x * blockDim.x + threadIdx.x;
    if (i < M) dinv[i] = rsqrtf((float)deg[i] + 1.0f);
}

__global__ void count_nodes_kernel(const int* __restrict__ batch, float* __restrict__ cnt, int M) {
    int i = blockIdx.x * blockDim.x + threadIdx.x;
    if (i < M) atomicAdd(&cnt[batch[i]], 1.0f);
}

// single-block exclusive prefix scan over deg -> off (also writes off[M] and cursor copy)
__global__ __launch_bounds__(1024)
void scan_offsets_kernel(const int* __restrict__ deg, int* __restrict__ off,
                         int* __restrict__ cursor, int M) {
    __shared__ int part[1024];
    int t = threadIdx.x;
    int chunk = (M + 1023) >> 10;
    int base = t * chunk;
    int s = 0;
    for (int i = 0; i < chunk; i++) { int j = base + i; if (j < M) s += deg[j]; }
    part[t] = s;
    __syncthreads();
    for (int d = 1; d < 1024; d <<= 1) {
        int add = (t >= d) ? part[t - d] : 0;
        __syncthreads();
        part[t] += add;
        __syncthreads();
    }
    int excl = part[t] - s;
    int run = excl;
    for (int i = 0; i < chunk; i++) {
        int j = base + i;
        if (j < M) { off[j] = run; cursor[j] = run; run += deg[j]; }
    }
    if (t == 1023) off[M] = part[1023];
}

__global__ void csr_fill_kernel(const int* __restrict__ src, const int* __restrict__ dst,
                                int* __restrict__ cursor, int* __restrict__ csr, int E) {
    int i = blockIdx.x * blockDim.x + threadIdx.x;
    if (i < E) {
        int p = atomicAdd(&cursor[dst[i]], 1);
        csr[p] = src[i];
    }
}

// ---------------- per-hop neighbor gather (replaces memset+scatter+combine) ----------------
// g[n] = dinv[n] * ( u[n] + sum_{s in N(n)} u[s] ) + b_gcn
// where u is already row-scaled by dinv in the preceding GEMM.
__global__ __launch_bounds__(256)
void gather_kernel(const int* __restrict__ off, const int* __restrict__ csr,
                   const float* __restrict__ u, const float* __restrict__ dinv,
                   const float* __restrict__ bgcn, float* __restrict__ g, int M) {
    int n = (blockIdx.x * blockDim.x + threadIdx.x) >> 5;
    if (n >= M) return;
    int lane = threadIdx.x & 31;
    int e0 = off[n], e1 = off[n + 1];
    float4 acc = *(const float4*)(u + (size_t)n * DL_ + lane * 4);   // self term
    int e = e0;
    // unrolled-by-2 with index prefetch for MLP
    for (; e + 1 < e1; e += 2) {
        int s0 = csr[e], s1 = csr[e + 1];
        float4 v0 = *(const float4*)(u + (size_t)s0 * DL_ + lane * 4);
        float4 v1 = *(const float4*)(u + (size_t)s1 * DL_ + lane * 4);
        acc.x += v0.x + v1.x;
        acc.y += v0.y + v1.y;
        acc.z += v0.z + v1.z;
        acc.w += v0.w + v1.w;
    }
    if (e < e1) {
        int s0 = csr[e];
        float4 v0 = *(const float4*)(u + (size_t)s0 * DL_ + lane * 4);
        acc.x += v0.x; acc.y += v0.y; acc.z += v0.z; acc.w += v0.w;
    }
    float dv = dinv[n];
    float4 b = *(const float4*)(bgcn + lane * 4);
    float4 o;
    o.x = fmaf(dv, acc.x, b.x);
    o.y = fmaf(dv, acc.y, b.y);
    o.z = fmaf(dv, acc.z, b.z);
    o.w = fmaf(dv, acc.w, b.w);
    *(float4*)(g + (size_t)n * DL_ + lane * 4) = o;
}

// ---------------- packed-f32x2 SGEMM ----------------
// C = act(A[M,K] @ B[K,Nc] + bias) * rowscale
// act: 0=none, 1=sigmoid, 2=relu, 3=softplus(v-5),
//      4=softplus(v-5) -> C (=std), and H = MU + C*EPS (fused reparam)
__global__ __launch_bounds__(128, 4)
void gemm_f32x2(const float* __restrict__ A, const float* __restrict__ B,
                const float* __restrict__ bias, const float* __restrict__ rowscale,
                float* __restrict__ C, int M, int K, int Nc, int act,
                const float* __restrict__ MU, const float* __restrict__ EPS,
                float* __restrict__ H) {
    __shared__ float As[2][8][64];
    __shared__ float Bs[2][8][128];
    const int tid  = threadIdx.x;
    const int tx   = tid & 15;
    const int ty   = tid >> 4;
    const int brow = blockIdx.x * 64;
    const int bcol = blockIdx.y * 128;

    const int arow = tid >> 1;
    const int acol = (tid & 1) * 4;
    const int bkr  = tid >> 4;
    const int bc   = (tid & 15) * 8;

    unsigned long long acc2[8][4];
#pragma unroll
    for (int i = 0; i < 8; i++)
#pragma unroll
        for (int j = 0; j < 4; j++) acc2[i][j] = 0ULL;

    const int nk = K >> 3;
    const int gr = brow + arow;

    {
        float4 av = make_float4(0.f, 0.f, 0.f, 0.f);
        if (gr < M) av = *(const float4*)(A + (size_t)gr * K + acol);
        As[0][acol + 0][arow] = av.x;
        As[0][acol + 1][arow] = av.y;
        As[0][acol + 2][arow] = av.z;
        As[0][acol + 3][arow] = av.w;
        float4 bv0 = *(const float4*)(B + (size_t)bkr * Nc + bcol + bc);
        float4 bv1 = *(const float4*)(B + (size_t)bkr * Nc + bcol + bc + 4);
        *(float4*)&Bs[0][bkr][bc]     = bv0;
        *(float4*)&Bs[0][bkr][bc + 4] = bv1;
    }
    __syncthreads();

    for (int it = 0; it < nk; ++it) {
        const int buf = it & 1;
        float4 nav = make_float4(0.f, 0.f, 0.f, 0.f);
        float4 nbv0, nbv1;
        const bool more = (it + 1) < nk;
        if (more) {
            int k0 = (it + 1) * 8;
            if (gr < M) nav = *(const float4*)(A + (size_t)gr * K + k0 + acol);
            nbv0 = *(const float4*)(B + (size_t)(k0 + bkr) * Nc + bcol + bc);
            nbv1 = *(const float4*)(B + (size_t)(k0 + bkr) * Nc + bcol + bc + 4);
        }
#pragma unroll
        for (int kk = 0; kk < 8; ++kk) {
            float ar[8], br[8];
            *(float4*)&ar[0] = *(const float4*)&As[buf][kk][ty * 8];
            *(float4*)&ar[4] = *(const float4*)&As[buf][kk][ty * 8 + 4];
            *(float4*)&br[0] = *(const float4*)&Bs[buf][kk][tx * 8];
            *(float4*)&br[4] = *(const float4*)&Bs[buf][kk][tx * 8 + 4];
            unsigned long long b2[4];
            PACK2(b2[0], br[0], br[1]);
            PACK2(b2[1], br[2], br[3]);
            PACK2(b2[2], br[4], br[5]);
            PACK2(b2[3], br[6], br[7]);
#pragma unroll
            for (int i = 0; i < 8; i++) {
                unsigned long long a2;
                PACK2(a2, ar[i], ar[i]);
                FMA2(acc2[i][0], a2, b2[0]);
                FMA2(acc2[i][1], a2, b2[1]);
                FMA2(acc2[i][2], a2, b2[2]);
                FMA2(acc2[i][3], a2, b2[3]);
            }
        }
        if (more) {
            As[buf ^ 1][acol + 0][arow] = nav.x;
            As[buf ^ 1][acol + 1][arow] = nav.y;
            As[buf ^ 1][acol + 2][arow] = nav.z;
            As[buf ^ 1][acol + 3][arow] = nav.w;
            *(float4*)&Bs[buf ^ 1][bkr][bc]     = nbv0;
            *(float4*)&Bs[buf ^ 1][bkr][bc + 4] = nbv1;
        }
        __syncthreads();
    }

#pragma unroll
    for (int i = 0; i < 8; i++) {
        int row = brow + ty * 8 + i;
        if (row >= M) continue;
        float rs = rowscale ? rowscale[row] : 1.0f;
#pragma unroll
        for (int jp = 0; jp < 4; jp++) {
            float v0, v1;
            UNPACK2(v0, v1, acc2[i][jp]);
            int col = bcol + tx * 8 + jp * 2;
            size_t idx = (size_t)row * Nc + col;
            if (bias) { v0 += bias[col]; v1 += bias[col + 1]; }
            if (act == 1) {
                v0 = 1.0f / (1.0f + expf(-v0));
                v1 = 1.0f / (1.0f + expf(-v1));
            } else if (act == 2) {
                v0 = fmaxf(v0, 0.0f);
                v1 = fmaxf(v1, 0.0f);
            } else if (act >= 3) {
                v0 -= 5.0f; v0 = (v0 > 20.0f) ? v0 : log1pf(expf(v0));
                v1 -= 5.0f; v1 = (v1 > 20.0f) ? v1 : log1pf(expf(v1));
            }
            float2 o; o.x = v0 * rs; o.y = v1 * rs;
            *(float2*)(C + idx) = o;
            if (act == 4) {
                float2 m = *(const float2*)(MU + idx);
                float2 e = *(const float2*)(EPS + idx);
                float2 hh;
                hh.x = fmaf(o.x, e.x, m.x);
                hh.y = fmaf(o.y, e.y, m.y);
                *(float2*)(H + idx) = hh;
            }
        }
    }
}

// ---------------- fused decoder tail: [N,128] -> 64 -> 32 -> 16 -> 10 -> sigmoid -> pool-sum ----------------
__global__ __launch_bounds__(128)
void decoder_tail_kernel(const float* __restrict__ din,
                         const float* __restrict__ W2, const float* __restrict__ b2,
                         const float* __restrict__ W3, const float* __restrict__ b3,
                         const float* __restrict__ W4, const float* __restrict__ b4,
                         const float* __restrict__ Wo, const float* __restrict__ bo,
                         const int* __restrict__ batch, float* __restrict__ sums, int M) {
    __shared__ float w2[128 * 64];
    __shared__ float w3[64 * 32];
    __shared__ float w4[32 * 16];
    __shared__ float wo[160];
    __shared__ float xs [4][128];
    __shared__ float t64[4][64];
    __shared__ float t32[4][32];
    __shared__ float t16[4][16];
    for (int i = threadIdx.x; i < 128 * 64; i += 128) w2[i] = W2[i];
    for (int i = threadIdx.x; i < 64 * 32;  i += 128) w3[i] = W3[i];
    for (int i = threadIdx.x; i < 32 * 16;  i += 128) w4[i] = W4[i];
    for (int i = threadIdx.x; i < 160;      i += 128) wo[i] = Wo[i];
    __syncthreads();

    int warp = threadIdx.x >> 5;
    int lane = threadIdx.x & 31;
    int stride = gridDim.x * 4;

    for (int row = blockIdx.x * 4 + warp; row < M; row += stride) {
        *(float4*)&xs[warp][lane * 4] = *(const float4*)(din + (size_t)row * 128 + lane * 4);
        __syncwarp();
        float s0 = b2[lane], s1 = b2[lane + 32];
#pragma unroll 8
        for (int k = 0; k < 128; k++) {
            float xv = xs[warp][k];
            s0 = fmaf(xv, w2[k * 64 + lane],      s0);
            s1 = fmaf(xv, w2[k * 64 + lane + 32], s1);
        }
        t64[warp][lane]      = fmaxf(s0, 0.0f);
        t64[warp][lane + 32] = fmaxf(s1, 0.0f);
        __syncwarp();
        float s = b3[lane];
#pragma unroll 8
        for (int k = 0; k < 64; k++) s = fmaf(t64[warp][k], w3[k * 32 + lane], s);
        t32[warp][lane] = fmaxf(s, 0.0f);
        __syncwarp();
        if (lane < 16) {
            float t = b4[lane];
#pragma unroll
            for (int k = 0; k < 32; k++) t = fmaf(t32[warp][k], w4[k * 16 + lane], t);
            t16[warp][lane] = fmaxf(t, 0.0f);
        }
        __syncwarp();
        if (lane < 10) {
            float t = bo[lane];
#pragma unroll
            for (int k = 0; k < 16; k++) t = fmaf(t16[warp][k], wo[k * 10 + lane], t);
            float yp = 1.0f / (1.0f + expf(-t));
            atomicAdd(&sums[batch[row] * 10 + lane], yp);
        }
        __syncwarp();
    }
}

__global__ void pool_finalize_kernel(const float* __restrict__ sums, const float* __restrict__ cnt,
                                     const float* __restrict__ y,
                                     float* __restrict__ out_pred, float* __restrict__ out_y) {
    int i = blockIdx.x * blockDim.x + threadIdx.x;
    if (i < GG * DOUT_) {
        out_pred[i] = sums[i] / fmaxf(cnt[i / DOUT_], 1.0f);
        out_y[i]    = y[i];
    }
}

// ---------------- launch ----------------
extern "C" void kernel_launch(void* const* d_in, const int* in_sizes, int n_in,
                              void* d_out, int out_size) {
    const float* x     = (const float*)d_in[0];
    const int*   ei    = (const int*)  d_in[1];
    const int*   batch = (const int*)  d_in[2];
    const float* y     = (const float*)d_in[3];
    const float* eps   = (const float*)d_in[4];
    const float* W_in  = (const float*)d_in[5];
    const float* b_in  = (const float*)d_in[6];
    const float* W_gcn = (const float*)d_in[7];
    const float* b_gcn = (const float*)d_in[8];
    const float* W_enc = (const float*)d_in[9];
    const float* b_enc = (const float*)d_in[10];
    const float* W_mu  = (const float*)d_in[11];
    const float* b_mu  = (const float*)d_in[12];
    const float* W_std = (const float*)d_in[13];
    const float* b_std = (const float*)d_in[14];
    const float* Wd0 = (const float*)d_in[15]; const float* bd0 = (const float*)d_in[16];
    const float* Wd1 = (const float*)d_in[17]; const float* bd1 = (const float*)d_in[18];
    const float* Wd2 = (const float*)d_in[19]; const float* bd2 = (const float*)d_in[20];
    const float* Wd3 = (const float*)d_in[21]; const float* bd3 = (const float*)d_in[22];
    const float* Wd4 = (const float*)d_in[23]; const float* bd4 = (const float*)d_in[24];
    const float* Wo  = (const float*)d_in[25]; const float* bo  = (const float*)d_in[26];

    float *h, *u, *gbuf, *tbuf, *dec1, *dinv, *sums, *cnt;
    int *deg, *off, *cur, *csr;
    cudaGetSymbolAddress((void**)&h,    g_h);
    cudaGetSymbolAddress((void**)&u,    g_u);
    cudaGetSymbolAddress((void**)&gbuf, g_g);
    cudaGetSymbolAddress((void**)&tbuf, g_t);
    cudaGetSymbolAddress((void**)&dec1, g_dec1);
    cudaGetSymbolAddress((void**)&dinv, g_dinv);
    cudaGetSymbolAddress((void**)&deg,  g_deg);
    cudaGetSymbolAddress((void**)&off,  g_off);
    cudaGetSymbolAddress((void**)&cur,  g_cur);
    cudaGetSymbolAddress((void**)&csr,  g_csr);
    cudaGetSymbolAddress((void**)&sums, g_sums);
    cudaGetSymbolAddress((void**)&cnt,  g_cnt);

    float* out      = (float*)d_out;
    float* out_pred = out;
    float* out_mu   = out + GG * DOUT_;
    float* out_std  = out + GG * DOUT_ + (size_t)NN * DL_;
    float* out_y    = out + GG * DOUT_ + (size_t)2 * NN * DL_;

    const int* src = ei;
    const int* dst = ei + EE;

    // one-time graph preprocessing
    cudaMemsetAsync(deg,  0, NN * sizeof(int));
    cudaMemsetAsync(sums, 0, GG * DOUT_ * sizeof(float));
    cudaMemsetAsync(cnt,  0, GG * sizeof(float));
    count_deg_kernel   <<<(EE + 255) / 256, 256>>>(dst, deg, EE);
    calc_dinv_kernel   <<<(NN + 255) / 256, 256>>>(deg, dinv, NN);
    scan_offsets_kernel<<<1, 1024>>>(deg, off, cur, NN);
    csr_fill_kernel    <<<(EE + 255) / 256, 256>>>(src, dst, cur, csr, EE);
    count_nodes_kernel <<<(NN + 255) / 256, 256>>>(batch, cnt, NN);

    dim3 g64((NN + 63) / 64, 1);
    gemm_f32x2<<<g64, 128>>>(x, W_in, b_in, nullptr, h, NN, DIN_, DL_, 1,
                             nullptr, nullptr, nullptr);

    for (int it = 0; it < KK; it++) {
        // u = (h @ W_gcn) * dinv[row]
        gemm_f32x2<<<g64, 128>>>(h, W_gcn, nullptr, dinv, u, NN, DL_, DL_, 0,
                                 nullptr, nullptr, nullptr);
        // g = dinv * (u + sum_neighbors u) + b_gcn
        gather_kernel<<<(NN * 32 + 255) / 256, 256>>>(off, csr, u, dinv, b_gcn, gbuf, NN);

        const float* curp = gbuf;
        float* nxt = tbuf;
        for (int j = 0; j < 5; j++) {
            gemm_f32x2<<<g64, 128>>>(curp, W_enc + (size_t)j * DL_ * DL_, b_enc + j * DL_,
                                     nullptr, nxt, NN, DL_, DL_, 1,
                                     nullptr, nullptr, nullptr);
            float* tmp = (float*)curp; curp = nxt; nxt = tmp;
        }
        gemm_f32x2<<<g64, 128>>>(curp, W_mu,  b_mu,  nullptr, out_mu,  NN, DL_, DL_, 0,
                                 nullptr, nullptr, nullptr);
        // std GEMM + fused reparam: writes out_std and h = mu + std*eps
        gemm_f32x2<<<g64, 128>>>(curp, W_std, b_std, nullptr, out_std, NN, DL_, DL_, 4,
                                 out_mu, eps + (size_t)it * NN * DL_, h);
    }

    // decoder
    dim3 gd0((NN + 63) / 64, 2);
    gemm_f32x2<<<gd0, 128>>>(h, Wd0, bd0, nullptr, dec1, NN, DL_, 256, 2,
                             nullptr, nullptr, nullptr);
    gemm_f32x2<<<g64, 128>>>(dec1, Wd1, bd1, nullptr, u, NN, 256, DL_, 2,
                             nullptr, nullptr, nullptr);
    decoder_tail_kernel<<<592, 128>>>(u, Wd2, bd2, Wd3, bd3, Wd4, bd4, Wo, bo,
                                      batch, sums, NN);
    pool_finalize_kernel<<<(GG * DOUT_ + 255) / 256, 256>>>(sums, cnt, y, out_pred, out_y);

    (void)in_sizes; (void)n_in; (void)out_size;
}

// round 4
// speedup vs baseline: 1.3988x; 1.1198x over previous
#include <cuda_runtime.h>
#include <math.h>

#define NN   50000
#define EE   800000
#define DIN_ 32
#define DL_  128
#define DOUT_ 10
#define GG   256
#define KK   3

// ---------------- scratch (device globals) ----------------
__device__ __align__(16) float g_h  [NN * DL_];
__device__ __align__(16) float g_u  [NN * DL_];
__device__ __align__(16) float g_g  [NN * DL_];
__device__ __align__(16) float g_t  [NN * DL_];
__device__ __align__(16) float g_dec1[NN * 256];
__device__ __align__(16) float g_dinv[NN];
__device__ __align__(16) int   g_deg [NN];
__device__ __align__(16) int   g_off [NN + 1];
__device__ __align__(16) int   g_cur [NN];
__device__ __align__(16) int   g_csr [EE];
__device__ __align__(16) float g_sums[GG * DOUT_];
__device__ __align__(16) float g_cnt [GG];

// ---------------- packed f32x2 helpers ----------------
#define PACK2(out, lo, hi) \
    asm("mov.b64 %0, {%1, %2};" : "=l"(out) : "r"(__float_as_uint(lo)), "r"(__float_as_uint(hi)))
#define UNPACK2(lo, hi, in) \
    do { unsigned _ulo, _uhi; \
         asm("mov.b64 {%0, %1}, %2;" : "=r"(_ulo), "=r"(_uhi) : "l"(in)); \
         lo = __uint_as_float(_ulo); hi = __uint_as_float(_uhi); } while (0)
#define FMA2(d, a, b) \
    asm("fma.rn.f32x2 %0, %1, %2, %0;" : "+l"(d) : "l"(a), "l"(b))

// ---------------- one-time graph preprocessing ----------------
__global__ void count_deg_kernel(const int* __restrict__ dst, int* __restrict__ deg, int E) {
    int i = blockIdx.x * blockDim.x + threadIdx.x;
    if (i < E) atomicAdd(&deg[dst[i]], 1);
}

__global__ void calc_dinv_kernel(const int* __restrict__ deg, float* __restrict__ dinv, int M) {
    int i = blockIdx.x * blockDim.x + threadIdx.x;
    if (i < M) dinv[i] = rsqrtf((float)deg[i] + 1.0f);
}

__global__ void count_nodes_kernel(const int* __restrict__ batch, float* __restrict__ cnt, int M) {
    int i = blockIdx.x * blockDim.x + threadIdx.x;
    if (i < M) atomicAdd(&cnt[batch[i]], 1.0f);
}

// single-block exclusive prefix scan over deg -> off (also writes off[M] and cursor copy)
__global__ __launch_bounds__(1024)
void scan_offsets_kernel(const int* __restrict__ deg, int* __restrict__ off,
                         int* __restrict__ cursor, int M) {
    __shared__ int part[1024];
    int t = threadIdx.x;
    int chunk = (M + 1023) >> 10;
    int base = t * chunk;
    int s = 0;
    for (int i = 0; i < chunk; i++) { int j = base + i; if (j < M) s += deg[j]; }
    part[t] = s;
    __syncthreads();
    for (int d = 1; d < 1024; d <<= 1) {
        int add = (t >= d) ? part[t - d] : 0;
        __syncthreads();
        part[t] += add;
        __syncthreads();
    }
    int excl = part[t] - s;
    int run = excl;
    for (int i = 0; i < chunk; i++) {
        int j = base + i;
        if (j < M) { off[j] = run; cursor[j] = run; run += deg[j]; }
    }
    if (t == 1023) off[M] = part[1023];
}

__global__ void csr_fill_kernel(const int* __restrict__ src, const int* __restrict__ dst,
                                int* __restrict__ cursor, int* __restrict__ csr, int E) {
    int i = blockIdx.x * blockDim.x + threadIdx.x;
    if (i < E) {
        int p = atomicAdd(&cursor[dst[i]], 1);
        csr[p] = src[i];
    }
}

// ---------------- per-hop neighbor gather ----------------
// g[n] = dinv[n] * ( u[n] + sum_{s in N(n)} u[s] ) + b_gcn
// One warp per node. Indices fetched 32-at-a-time via lane load + shfl;
// neighbor rows loaded in 8-deep batches for MLP=8.
__global__ __launch_bounds__(256)
void gather_kernel(const int* __restrict__ off, const int* __restrict__ csr,
                   const float* __restrict__ u, const float* __restrict__ dinv,
                   const float* __restrict__ bgcn, float* __restrict__ g, int M) {
    int n = (blockIdx.x * blockDim.x + threadIdx.x) >> 5;
    if (n >= M) return;
    int lane = threadIdx.x & 31;
    int e0 = off[n], e1 = off[n + 1];
    int deg = e1 - e0;

    float4 acc = __ldg((const float4*)(u + (size_t)n * DL_ + lane * 4));   // self term

    for (int base = 0; base < deg; base += 32) {
        int cnt = min(32, deg - base);
        int idx = 0;
        if (base + lane < deg) idx = __ldg(csr + e0 + base + lane);
        int j = 0;
        for (; j + 8 <= cnt; j += 8) {
            float4 v[8];
#pragma unroll
            for (int q = 0; q < 8; q++) {
                int s = __shfl_sync(0xffffffffu, idx, j + q);
                v[q] = __ldg((const float4*)(u + (size_t)s * DL_ + lane * 4));
            }
#pragma unroll
            for (int q = 0; q < 8; q++) {
                acc.x += v[q].x; acc.y += v[q].y; acc.z += v[q].z; acc.w += v[q].w;
            }
        }
        if (j + 4 <= cnt) {
            float4 v[4];
#pragma unroll
            for (int q = 0; q < 4; q++) {
                int s = __shfl_sync(0xffffffffu, idx, j + q);
                v[q] = __ldg((const float4*)(u + (size_t)s * DL_ + lane * 4));
            }
#pragma unroll
            for (int q = 0; q < 4; q++) {
                acc.x += v[q].x; acc.y += v[q].y; acc.z += v[q].z; acc.w += v[q].w;
            }
            j += 4;
        }
        for (; j < cnt; j++) {
            int s = __shfl_sync(0xffffffffu, idx, j);
            float4 v = __ldg((const float4*)(u + (size_t)s * DL_ + lane * 4));
            acc.x += v.x; acc.y += v.y; acc.z += v.z; acc.w += v.w;
        }
    }

    float dv = dinv[n];
    float4 b = *(const float4*)(bgcn + lane * 4);
    float4 o;
    o.x = fmaf(dv, acc.x, b.x);
    o.y = fmaf(dv, acc.y, b.y);
    o.z = fmaf(dv, acc.z, b.z);
    o.w = fmaf(dv, acc.w, b.w);
    *(float4*)(g + (size_t)n * DL_ + lane * 4) = o;
}

// ---------------- packed-f32x2 SGEMM ----------------
// C = act(A[M,K] @ B[K,Nc] + bias) * rowscale
// act: 0=none, 1=sigmoid, 2=relu, 3=softplus(v-5),
//      4=softplus(v-5) -> C (=std), and H = MU + C*EPS (fused reparam)
__global__ __launch_bounds__(128, 4)
void gemm_f32x2(const float* __restrict__ A, const float* __restrict__ B,
                const float* __restrict__ bias, const float* __restrict__ rowscale,
                float* __restrict__ C, int M, int K, int Nc, int act,
                const float* __restrict__ MU, const float* __restrict__ EPS,
                float* __restrict__ H) {
    __shared__ float As[2][8][64];
    __shared__ float Bs[2][8][128];
    const int tid  = threadIdx.x;
    const int tx   = tid & 15;
    const int ty   = tid >> 4;
    const int brow = blockIdx.x * 64;
    const int bcol = blockIdx.y * 128;

    const int arow = tid >> 1;
    const int acol = (tid & 1) * 4;
    const int bkr  = tid >> 4;
    const int bc   = (tid & 15) * 8;

    unsigned long long acc2[8][4];
#pragma unroll
    for (int i = 0; i < 8; i++)
#pragma unroll
        for (int j = 0; j < 4; j++) acc2[i][j] = 0ULL;

    const int nk = K >> 3;
    const int gr = brow + arow;

    {
        float4 av = make_float4(0.f, 0.f, 0.f, 0.f);
        if (gr < M) av = *(const float4*)(A + (size_t)gr * K + acol);
        As[0][acol + 0][arow] = av.x;
        As[0][acol + 1][arow] = av.y;
        As[0][acol + 2][arow] = av.z;
        As[0][acol + 3][arow] = av.w;
        float4 bv0 = *(const float4*)(B + (size_t)bkr * Nc + bcol + bc);
        float4 bv1 = *(const float4*)(B + (size_t)bkr * Nc + bcol + bc + 4);
        *(float4*)&Bs[0][bkr][bc]     = bv0;
        *(float4*)&Bs[0][bkr][bc + 4] = bv1;
    }
    __syncthreads();

    for (int it = 0; it < nk; ++it) {
        const int buf = it & 1;
        float4 nav = make_float4(0.f, 0.f, 0.f, 0.f);
        float4 nbv0, nbv1;
        const bool more = (it + 1) < nk;
        if (more) {
            int k0 = (it + 1) * 8;
            if (gr < M) nav = *(const float4*)(A + (size_t)gr * K + k0 + acol);
            nbv0 = *(const float4*)(B + (size_t)(k0 + bkr) * Nc + bcol + bc);
            nbv1 = *(const float4*)(B + (size_t)(k0 + bkr) * Nc + bcol + bc + 4);
        }
#pragma unroll
        for (int kk = 0; kk < 8; ++kk) {
            float ar[8], br[8];
            *(float4*)&ar[0] = *(const float4*)&As[buf][kk][ty * 8];
            *(float4*)&ar[4] = *(const float4*)&As[buf][kk][ty * 8 + 4];
            *(float4*)&br[0] = *(const float4*)&Bs[buf][kk][tx * 8];
            *(float4*)&br[4] = *(const float4*)&Bs[buf][kk][tx * 8 + 4];
            unsigned long long b2[4];
            PACK2(b2[0], br[0], br[1]);
            PACK2(b2[1], br[2], br[3]);
            PACK2(b2[2], br[4], br[5]);
            PACK2(b2[3], br[6], br[7]);
#pragma unroll
            for (int i = 0; i < 8; i++) {
                unsigned long long a2;
                PACK2(a2, ar[i], ar[i]);
                FMA2(acc2[i][0], a2, b2[0]);
                FMA2(acc2[i][1], a2, b2[1]);
                FMA2(acc2[i][2], a2, b2[2]);
                FMA2(acc2[i][3], a2, b2[3]);
            }
        }
        if (more) {
            As[buf ^ 1][acol + 0][arow] = nav.x;
            As[buf ^ 1][acol + 1][arow] = nav.y;
            As[buf ^ 1][acol + 2][arow] = nav.z;
            As[buf ^ 1][acol + 3][arow] = nav.w;
            *(float4*)&Bs[buf ^ 1][bkr][bc]     = nbv0;
            *(float4*)&Bs[buf ^ 1][bkr][bc + 4] = nbv1;
        }
        __syncthreads();
    }

#pragma unroll
    for (int i = 0; i < 8; i++) {
        int row = brow + ty * 8 + i;
        if (row >= M) continue;
        float rs = rowscale ? rowscale[row] : 1.0f;
#pragma unroll
        for (int jp = 0; jp < 4; jp++) {
            float v0, v1;
            UNPACK2(v0, v1, acc2[i][jp]);
            int col = bcol + tx * 8 + jp * 2;
            size_t idx = (size_t)row * Nc + col;
            if (bias) { v0 += bias[col]; v1 += bias[col + 1]; }
            if (act == 1) {
                v0 = __fdividef(1.0f, 1.0f + __expf(-v0));
                v1 = __fdividef(1.0f, 1.0f + __expf(-v1));
            } else if (act == 2) {
                v0 = fmaxf(v0, 0.0f);
                v1 = fmaxf(v1, 0.0f);
            } else if (act >= 3) {
                v0 -= 5.0f; v0 = (v0 > 20.0f) ? v0 : log1pf(expf(v0));
                v1 -= 5.0f; v1 = (v1 > 20.0f) ? v1 : log1pf(expf(v1));
            }
            float2 o; o.x = v0 * rs; o.y = v1 * rs;
            *(float2*)(C + idx) = o;
            if (act == 4) {
                float2 m = *(const float2*)(MU + idx);
                float2 e = *(const float2*)(EPS + idx);
                float2 hh;
                hh.x = fmaf(o.x, e.x, m.x);
                hh.y = fmaf(o.y, e.y, m.y);
                *(float2*)(H + idx) = hh;
            }
        }
    }
}

// ---------------- fused decoder tail: [N,128] -> 64 -> 32 -> 16 -> 10 -> sigmoid -> pool-sum ----------------
__global__ __launch_bounds__(128)
void decoder_tail_kernel(const float* __restrict__ din,
                         const float* __restrict__ W2, const float* __restrict__ b2,
                         const float* __restrict__ W3, const float* __restrict__ b3,
                         const float* __restrict__ W4, const float* __restrict__ b4,
                         const float* __restrict__ Wo, const float* __restrict__ bo,
                         const int* __restrict__ batch, float* __restrict__ sums, int M) {
    __shared__ float w2[128 * 64];
    __shared__ float w3[64 * 32];
    __shared__ float w4[32 * 16];
    __shared__ float wo[160];
    __shared__ float xs [4][128];
    __shared__ float t64[4][64];
    __shared__ float t32[4][32];
    __shared__ float t16[4][16];
    for (int i = threadIdx.x; i < 128 * 64; i += 128) w2[i] = W2[i];
    for (int i = threadIdx.x; i < 64 * 32;  i += 128) w3[i] = W3[i];
    for (int i = threadIdx.x; i < 32 * 16;  i += 128) w4[i] = W4[i];
    for (int i = threadIdx.x; i < 160;      i += 128) wo[i] = Wo[i];
    __syncthreads();

    int warp = threadIdx.x >> 5;
    int lane = threadIdx.x & 31;
    int stride = gridDim.x * 4;

    for (int row = blockIdx.x * 4 + warp; row < M; row += stride) {
        *(float4*)&xs[warp][lane * 4] = *(const float4*)(din + (size_t)row * 128 + lane * 4);
        __syncwarp();
        float s0 = b2[lane], s1 = b2[lane + 32];
#pragma unroll 8
        for (int k = 0; k < 128; k++) {
            float xv = xs[warp][k];
            s0 = fmaf(xv, w2[k * 64 + lane],      s0);
            s1 = fmaf(xv, w2[k * 64 + lane + 32], s1);
        }
        t64[warp][lane]      = fmaxf(s0, 0.0f);
        t64[warp][lane + 32] = fmaxf(s1, 0.0f);
        __syncwarp();
        float s = b3[lane];
#pragma unroll 8
        for (int k = 0; k < 64; k++) s = fmaf(t64[warp][k], w3[k * 32 + lane], s);
        t32[warp][lane] = fmaxf(s, 0.0f);
        __syncwarp();
        if (lane < 16) {
            float t = b4[lane];
#pragma unroll
            for (int k = 0; k < 32; k++) t = fmaf(t32[warp][k], w4[k * 16 + lane], t);
            t16[warp][lane] = fmaxf(t, 0.0f);
        }
        __syncwarp();
        if (lane < 10) {
            float t = bo[lane];
#pragma unroll
            for (int k = 0; k < 16; k++) t = fmaf(t16[warp][k], wo[k * 10 + lane], t);
            float yp = __fdividef(1.0f, 1.0f + __expf(-t));
            atomicAdd(&sums[batch[row] * 10 + lane], yp);
        }
        __syncwarp();
    }
}

__global__ void pool_finalize_kernel(const float* __restrict__ sums, const float* __restrict__ cnt,
                                     const float* __restrict__ y,
                                     float* __restrict__ out_pred, float* __restrict__ out_y) {
    int i = blockIdx.x * blockDim.x + threadIdx.x;
    if (i < GG * DOUT_) {
        out_pred[i] = sums[i] / fmaxf(cnt[i / DOUT_], 1.0f);
        out_y[i]    = y[i];
    }
}

// ---------------- launch ----------------
extern "C" void kernel_launch(void* const* d_in, const int* in_sizes, int n_in,
                              void* d_out, int out_size) {
    const float* x     = (const float*)d_in[0];
    const int*   ei    = (const int*)  d_in[1];
    const int*   batch = (const int*)  d_in[2];
    const float* y     = (const float*)d_in[3];
    const float* eps   = (const float*)d_in[4];
    const float* W_in  = (const float*)d_in[5];
    const float* b_in  = (const float*)d_in[6];
    const float* W_gcn = (const float*)d_in[7];
    const float* b_gcn = (const float*)d_in[8];
    const float* W_enc = (const float*)d_in[9];
    const float* b_enc = (const float*)d_in[10];
    const float* W_mu  = (const float*)d_in[11];
    const float* b_mu  = (const float*)d_in[12];
    const float* W_std = (const float*)d_in[13];
    const float* b_std = (const float*)d_in[14];
    const float* Wd0 = (const float*)d_in[15]; const float* bd0 = (const float*)d_in[16];
    const float* Wd1 = (const float*)d_in[17]; const float* bd1 = (const float*)d_in[18];
    const float* Wd2 = (const float*)d_in[19]; const float* bd2 = (const float*)d_in[20];
    const float* Wd3 = (const float*)d_in[21]; const float* bd3 = (const float*)d_in[22];
    const float* Wd4 = (const float*)d_in[23]; const float* bd4 = (const float*)d_in[24];
    const float* Wo  = (const float*)d_in[25]; const float* bo  = (const float*)d_in[26];

    float *h, *u, *gbuf, *tbuf, *dec1, *dinv, *sums, *cnt;
    int *deg, *off, *cur, *csr;
    cudaGetSymbolAddress((void**)&h,    g_h);
    cudaGetSymbolAddress((void**)&u,    g_u);
    cudaGetSymbolAddress((void**)&gbuf, g_g);
    cudaGetSymbolAddress((void**)&tbuf, g_t);
    cudaGetSymbolAddress((void**)&dec1, g_dec1);
    cudaGetSymbolAddress((void**)&dinv, g_dinv);
    cudaGetSymbolAddress((void**)&deg,  g_deg);
    cudaGetSymbolAddress((void**)&off,  g_off);
    cudaGetSymbolAddress((void**)&cur,  g_cur);
    cudaGetSymbolAddress((void**)&csr,  g_csr);
    cudaGetSymbolAddress((void**)&sums, g_sums);
    cudaGetSymbolAddress((void**)&cnt,  g_cnt);

    float* out      = (float*)d_out;
    float* out_pred = out;
    float* out_mu   = out + GG * DOUT_;
    float* out_std  = out + GG * DOUT_ + (size_t)NN * DL_;
    float* out_y    = out + GG * DOUT_ + (size_t)2 * NN * DL_;

    const int* src = ei;
    const int* dst = ei + EE;

    // one-time graph preprocessing
    cudaMemsetAsync(deg,  0, NN * sizeof(int));
    cudaMemsetAsync(sums, 0, GG * DOUT_ * sizeof(float));
    cudaMemsetAsync(cnt,  0, GG * sizeof(float));
    count_deg_kernel   <<<(EE + 255) / 256, 256>>>(dst, deg, EE);
    calc_dinv_kernel   <<<(NN + 255) / 256, 256>>>(deg, dinv, NN);
    scan_offsets_kernel<<<1, 1024>>>(deg, off, cur, NN);
    csr_fill_kernel    <<<(EE + 255) / 256, 256>>>(src, dst, cur, csr, EE);
    count_nodes_kernel <<<(NN + 255) / 256, 256>>>(batch, cnt, NN);

    dim3 g64((NN + 63) / 64, 1);
    gemm_f32x2<<<g64, 128>>>(x, W_in, b_in, nullptr, h, NN, DIN_, DL_, 1,
                             nullptr, nullptr, nullptr);

    for (int it = 0; it < KK; it++) {
        gemm_f32x2<<<g64, 128>>>(h, W_gcn, nullptr, dinv, u, NN, DL_, DL_, 0,
                                 nullptr, nullptr, nullptr);
        gather_kernel<<<(NN * 32 + 255) / 256, 256>>>(off, csr, u, dinv, b_gcn, gbuf, NN);

        const float* curp = gbuf;
        float* nxt = tbuf;
        for (int j = 0; j < 5; j++) {
            gemm_f32x2<<<g64, 128>>>(curp, W_enc + (size_t)j * DL_ * DL_, b_enc + j * DL_,
                                     nullptr, nxt, NN, DL_, DL_, 1,
                                     nullptr, nullptr, nullptr);
            float* tmp = (float*)curp; curp = nxt; nxt = tmp;
        }
        gemm_f32x2<<<g64, 128>>>(curp, W_mu,  b_mu,  nullptr, out_mu,  NN, DL_, DL_, 0,
                                 nullptr, nullptr, nullptr);
        gemm_f32x2<<<g64, 128>>>(curp, W_std, b_std, nullptr, out_std, NN, DL_, DL_, 4,
                                 out_mu, eps + (size_t)it * NN * DL_, h);
    }

    // decoder
    dim3 gd0((NN + 63) / 64, 2);
    gemm_f32x2<<<gd0, 128>>>(h, Wd0, bd0, nullptr, dec1, NN, DL_, 256, 2,
                             nullptr, nullptr, nullptr);
    gemm_f32x2<<<g64, 128>>>(dec1, Wd1, bd1, nullptr, u, NN, 256, DL_, 2,
                             nullptr, nullptr, nullptr);
    decoder_tail_kernel<<<592, 128>>>(u, Wd2, bd2, Wd3, bd3, Wd4, bd4, Wo, bo,
                                      batch, sums, NN);
    pool_finalize_kernel<<<(GG * DOUT_ + 255) / 256, 256>>>(sums, cnt, y, out_pred, out_y);

    (void)in_sizes; (void)n_in; (void)out_size;
}